// round 1
// baseline (speedup 1.0000x reference)
#include <cuda_runtime.h>

#define B_  256
#define T_  24
#define D_  2
#define NN  512
#define H_  128
#define G_  384            // 3*H
#define MT  64             // cells per block
#define NTH 256
#define KC  8              // k-chunk for weight streaming
#define NCHUNK (H_/KC)     // 16

#define CB_S 388           // Cbuf row stride (padded)
#define NX_S 132           // nx row stride (padded)

// SMEM layout (float offsets)
#define OFF_H0   0                         // h0 tile [128][64]
#define OFF_H1   8192                      // h1 tile [128][64]
#define OFF_CB   16384                     // gate buffer [64][388]
#define OFF_NX   (16384 + 64*CB_S)         // 41216: i_n buffer [64][132]
#define OFF_WS   (OFF_NX + 64*NX_S)        // 49664: W double-buffer [2][8][384]
#define OFF_WX0  (OFF_WS + 2*KC*G_)        // 55808: Wx0 [2][384]
#define OFF_XS   (OFF_WX0 + 2*G_)          // 56576: x slice [2][64]
#define SMEM_FLOATS (OFF_XS + 2*MT)        // 56704
#define SMEM_BYTES  (SMEM_FLOATS*4)        // 226816 (< 232448 limit)

#define PACK2(d, s)  asm("mov.b64 %0, {%1, %1};" : "=l"(d) : "f"(s))
#define FMA2(c, a, b) asm("fma.rn.f32x2 %0, %1, %2, %0;" : "+l"(c) : "l"(a), "l"(b))

__device__ __forceinline__ void cp_async16(float* s, const float* g) {
    unsigned int sa = (unsigned int)__cvta_generic_to_shared(s);
    asm volatile("cp.async.cg.shared.global [%0], [%1], 16;" :: "r"(sa), "l"(g));
}

__device__ __forceinline__ float sigf(float x) {
    // 1/(1+exp(-x)); saturates cleanly (exp->inf => 0, exp->0 => 1)
    return __fdividef(1.f, 1.f + __expf(-x));
}
__device__ __forceinline__ float tanhfast(float x) {
    // 2*sigmoid(2x)-1; no NaN at extremes
    return __fdividef(2.f, 1.f + __expf(-2.f * x)) - 1.f;
}

// C[64 cells][384 gates] = bias + hs[64][128] * W[128][384]
// MODE 0/1: store result to Cbuf.  MODE 2: cols<256 add into Cbuf, cols>=256 -> nx.
template<int MODE>
__device__ __forceinline__ void gemm384(
    const float* __restrict__ Wg, const float* __restrict__ bias,
    const float* __restrict__ hs, float* __restrict__ sm)
{
    const int tid = threadIdx.x;
    const int cg = tid & 7;        // 8 cell-groups * 8 cells
    const int gg = tid >> 3;       // 32 gate-groups * 12 gates
    float* Ws = sm + OFF_WS;
    float* Cb = sm + OFF_CB;
    float* nx = sm + OFF_NX;

    unsigned long long acc[8][6];
    #pragma unroll
    for (int j = 0; j < 6; j++) {
        unsigned long long p = *(const unsigned long long*)(bias + gg*12 + 2*j);
        #pragma unroll
        for (int i = 0; i < 8; i++) acc[i][j] = p;
    }

    // prologue: chunk 0 -> buf 0
    #pragma unroll
    for (int v = 0; v < 3; v++) {
        int idx = (tid + v*NTH) * 4;
        cp_async16(Ws + idx, Wg + idx);
    }
    asm volatile("cp.async.commit_group;");

    #pragma unroll 1
    for (int kc = 0; kc < NCHUNK; kc++) {
        const float* buf = Ws + (kc & 1) * (KC*G_);
        if (kc + 1 < NCHUNK) {
            float* nb = Ws + ((kc+1) & 1) * (KC*G_);
            const float* src = Wg + (kc+1)*KC*G_;
            #pragma unroll
            for (int v = 0; v < 3; v++) {
                int idx = (tid + v*NTH) * 4;
                cp_async16(nb + idx, src + idx);
            }
            asm volatile("cp.async.commit_group;");
            asm volatile("cp.async.wait_group 1;");
        } else {
            asm volatile("cp.async.wait_group 0;");
        }
        __syncthreads();

        const float* hk = hs + kc*KC*MT + cg*8;
        #pragma unroll
        for (int kk = 0; kk < KC; kk++) {
            float4 a0 = *(const float4*)(hk + kk*MT);
            float4 a1 = *(const float4*)(hk + kk*MT + 4);
            unsigned long long ap[8];
            PACK2(ap[0], a0.x); PACK2(ap[1], a0.y);
            PACK2(ap[2], a0.z); PACK2(ap[3], a0.w);
            PACK2(ap[4], a1.x); PACK2(ap[5], a1.y);
            PACK2(ap[6], a1.z); PACK2(ap[7], a1.w);
            const unsigned long long* br =
                (const unsigned long long*)(buf + kk*G_ + gg*12);
            unsigned long long b0 = br[0], b1 = br[1], b2 = br[2],
                               b3 = br[3], b4 = br[4], b5 = br[5];
            #pragma unroll
            for (int i = 0; i < 8; i++) {
                FMA2(acc[i][0], ap[i], b0);
                FMA2(acc[i][1], ap[i], b1);
                FMA2(acc[i][2], ap[i], b2);
                FMA2(acc[i][3], ap[i], b3);
                FMA2(acc[i][4], ap[i], b4);
                FMA2(acc[i][5], ap[i], b5);
            }
        }
        __syncthreads();
    }

    // writeback
    if (MODE < 2) {
        #pragma unroll
        for (int i = 0; i < 8; i++) {
            unsigned long long* crow =
                (unsigned long long*)(Cb + (cg*8 + i)*CB_S + gg*12);
            #pragma unroll
            for (int j = 0; j < 6; j++) crow[j] = acc[i][j];
        }
    } else {
        #pragma unroll
        for (int i = 0; i < 8; i++) {
            int m = cg*8 + i;
            #pragma unroll
            for (int j = 0; j < 6; j++) {
                int g = gg*12 + 2*j;
                float lo, hi;
                asm("mov.b64 {%0, %1}, %2;" : "=f"(lo), "=f"(hi) : "l"(acc[i][j]));
                if (g < 256) {
                    float2* p = (float2*)(Cb + m*CB_S + g);
                    float2 o = *p; o.x += lo; o.y += hi; *p = o;
                } else {
                    float2 v; v.x = lo; v.y = hi;
                    *(float2*)(nx + m*NX_S + (g - 256)) = v;
                }
            }
        }
    }
}

__global__ void __launch_bounds__(NTH, 1)
rnn_kernel(const float* __restrict__ x,
           const float* __restrict__ Wx0, const float* __restrict__ Wh0,
           const float* __restrict__ bx0, const float* __restrict__ bh0,
           const float* __restrict__ Wx1, const float* __restrict__ Wh1,
           const float* __restrict__ bx1, const float* __restrict__ bh1,
           float* __restrict__ out)
{
    extern __shared__ float sm[];
    const int tid = threadIdx.x;
    const int c0 = blockIdx.x * MT;
    const int bb = c0 >> 9;          // batch index (NN=512)
    const int n0 = c0 & (NN - 1);

    float* h0s  = sm + OFF_H0;   // [k][cell]
    float* h1s  = sm + OFF_H1;
    float* Cb   = sm + OFF_CB;
    float* nx   = sm + OFF_NX;
    float* wx0s = sm + OFF_WX0;
    float* xs   = sm + OFF_XS;

    for (int i = tid; i < 2*G_; i += NTH) wx0s[i] = Wx0[i];
    for (int i = tid; i < H_*MT; i += NTH) { h0s[i] = 0.f; h1s[i] = 0.f; }
    __syncthreads();

    for (int t = 0; t < T_; t++) {
        if (tid < 2*MT) {
            int d = tid >> 6, m = tid & (MT - 1);
            xs[tid] = x[((bb*T_ + t)*D_ + d)*NN + n0 + m];
        }

        // ---- layer 0: gh = bh0 + h0 * Wh0 ----
        gemm384<0>(Wh0, bh0, h0s, sm);
        __syncthreads();
        for (int it = tid; it < H_*MT; it += NTH) {
            int m = it & (MT - 1);
            int j = it >> 6;
            float x0 = xs[m], x1 = xs[MT + m];
            float ir  = bx0[j]        + x0*wx0s[j]        + x1*wx0s[G_ + j];
            float iz  = bx0[H_ + j]   + x0*wx0s[H_ + j]   + x1*wx0s[G_ + H_ + j];
            float inn = bx0[2*H_ + j] + x0*wx0s[2*H_ + j] + x1*wx0s[G_ + 2*H_ + j];
            const float* cr = Cb + m*CB_S;
            float r = sigf(ir + cr[j]);
            float z = sigf(iz + cr[H_ + j]);
            float n = tanhfast(inn + r*cr[2*H_ + j]);
            float hp = h0s[it];
            h0s[it] = (1.f - z)*n + z*hp;
        }

        // ---- layer 1: gh = bh1 + h1*Wh1 (-> Cbuf); gi = bx1 + h0new*Wx1 ----
        gemm384<1>(Wh1, bh1, h1s, sm);
        gemm384<2>(Wx1, bx1, h0s, sm);
        __syncthreads();
        for (int it = tid; it < H_*MT; it += NTH) {
            int m = it & (MT - 1);
            int j = it >> 6;
            const float* cr = Cb + m*CB_S;
            float r = sigf(cr[j]);             // gi_r + gh_r summed in Cbuf
            float z = sigf(cr[H_ + j]);
            float n = tanhfast(nx[m*NX_S + j] + r*cr[2*H_ + j]);
            float hp = h1s[it];
            h1s[it] = (1.f - z)*n + z*hp;
        }
    }

    __syncthreads();
    const int base0 = (bb*H_)*NN + n0;
    const int base1 = ((B_ + bb)*H_)*NN + n0;
    for (int it = tid; it < H_*MT; it += NTH) {
        int hh = it >> 6, m = it & (MT - 1);
        out[base0 + hh*NN + m] = h0s[it];
        out[base1 + hh*NN + m] = h1s[it];
    }
}

extern "C" void kernel_launch(void* const* d_in, const int* in_sizes, int n_in,
                              void* d_out, int out_size)
{
    const float* x   = (const float*)d_in[0];
    const float* Wx0 = (const float*)d_in[1];
    const float* Wh0 = (const float*)d_in[2];
    const float* bx0 = (const float*)d_in[3];
    const float* bh0 = (const float*)d_in[4];
    const float* Wx1 = (const float*)d_in[5];
    const float* Wh1 = (const float*)d_in[6];
    const float* bx1 = (const float*)d_in[7];
    const float* bh1 = (const float*)d_in[8];
    float* out = (float*)d_out;

    cudaFuncSetAttribute(rnn_kernel,
                         cudaFuncAttributeMaxDynamicSharedMemorySize, SMEM_BYTES);

    dim3 grid((B_ * NN) / MT);   // 2048 blocks, 64 cells each
    rnn_kernel<<<grid, NTH, SMEM_BYTES>>>(x, Wx0, Wh0, bx0, bh0,
                                          Wx1, Wh1, bx1, bh1, out);
}